// round 14
// baseline (speedup 1.0000x reference)
#include <cuda_runtime.h>

#define NN 50000
#define DD 64
#define HH 128
#define EE 500000
#define ZSZ (NN*DD)
#define EB 256          // edges per scatter block (= blockDim)

typedef unsigned long long ull;

// ---------------------------------------------------------------- scratch
__device__ float g_z[(size_t)8*ZSZ];   // 0-3 GAT planes, 4-7 GC planes
__device__ float g_s[4*NN];
__device__ float g_el[4*NN];
__device__ float g_er[4*NN];
__device__ float g_no[4*NN];
__device__ float g_ni[4*NN];
__device__ float g_wsum[8];

struct G4   { const int* s[4]; const int* d[4]; };
struct SaP  { const float* W1[4]; const float* b1[4]; const float* w2[4]; };
struct ScatP {
    const int* src[4]; const int* dst[4];
    const float* el[4]; const float* er[4];
    float* s[4]; const float* no[4];
    float* z[4];
    int gat[4];
};
struct PostP {
    int mode[4];            // 0 = GAT final, 1 = GC gemm
    const float* s[4];
    float* z[4];
    float* zn[4];           // plane to zero (or null)
    const float* W[4]; const float* b[4]; const float* ni[4];
};

// ---------------------------------------------------------------- utils
__device__ __forceinline__ ull pack2(float a, float b) {
    ull r; asm("mov.b64 %0, {%1,%2};" : "=l"(r) : "f"(a), "f"(b)); return r;
}
__device__ __forceinline__ void unpack2(ull v, float& a, float& b) {
    asm("mov.b64 {%0,%1}, %2;" : "=f"(a), "=f"(b) : "l"(v));
}
__device__ __forceinline__ ull ffma2(ull a, ull b, ull c) {
    ull d; asm("fma.rn.f32x2 %0, %1, %2, %3;" : "=l"(d) : "l"(a), "l"(b), "l"(c));
    return d;
}
__device__ __forceinline__ float tanha(float x) {
    float r; asm("tanh.approx.f32 %0, %1;" : "=f"(r) : "f"(x)); return r;
}
__device__ __forceinline__ float elu(float x) { return x > 0.f ? x : expm1f(x); }
__device__ __forceinline__ void red4(float* p, float a, float b, float c, float d) {
    asm volatile("red.global.add.v4.f32 [%0], {%1, %2, %3, %4};"
                 :: "l"(p), "f"(a), "f"(b), "f"(c), "f"(d));   // no mem clobber: keep MLP
}

// -------- fused prologue: y0 zero planes0/1+nodes; y1/y2 ler; y3 deg; y4 zero 6/7
__global__ void pre_k(float* __restrict__ zb,
                      const float* __restrict__ feat_user,
                      const float* __restrict__ feat_item,
                      const float* __restrict__ attn_l,
                      const float* __restrict__ attn_r,
                      G4 C) {
    int y = blockIdx.y;
    int gid = blockIdx.x * blockDim.x + threadIdx.x;      // up to 1.6M
    if (y == 0) {
        ((float4*)zb)[gid] = make_float4(0.f,0.f,0.f,0.f);   // planes 0,1
        if (gid < 4*NN) { g_s[gid] = 0.f; g_no[gid] = 0.f; g_ni[gid] = 0.f; }
        if (gid < 8) g_wsum[gid] = 0.f;
        return;
    }
    if (y == 4) {
        ((float4*)(zb + (size_t)6*ZSZ))[gid] = make_float4(0.f,0.f,0.f,0.f); // planes 6,7
        return;
    }
    if (y == 3) {
        #pragma unroll
        for (int k = 0; k < 2; k++) {
            int i = gid + k * 1600000;
            if (i < 4*EE) {
                int g = i / EE, e = i - g*EE;
                atomicAdd(g_no + g*NN + __ldg(C.s[g] + e), 1.f);
                atomicAdd(g_ni + g*NN + __ldg(C.d[g] + e), 1.f);
            }
        }
        return;
    }
    int tbl = y - 1;
    int w = gid >> 5;
    int lane = threadIdx.x & 31;
    const float* f = (tbl == 0 ? feat_user : feat_item) + (size_t)w * DD;
    float f0 = f[lane], f1 = f[lane + 32];
    const float* v0; const float* v1; const float* v2; const float* v3;
    if (tbl == 0) { v0 = attn_r; v1 = attn_r + DD; v2 = attn_l + 2*DD; v3 = attn_l + 3*DD; }
    else          { v0 = attn_l; v1 = attn_l + DD; v2 = attn_r + 2*DD; v3 = attn_r + 3*DD; }
    float s0 = f0*__ldg(v0+lane) + f1*__ldg(v0+lane+32);
    float s1 = f0*__ldg(v1+lane) + f1*__ldg(v1+lane+32);
    float s2 = f0*__ldg(v2+lane) + f1*__ldg(v2+lane+32);
    float s3 = f0*__ldg(v3+lane) + f1*__ldg(v3+lane+32);
    #pragma unroll
    for (int o = 16; o; o >>= 1) {
        s0 += __shfl_down_sync(0xffffffffu, s0, o);
        s1 += __shfl_down_sync(0xffffffffu, s1, o);
        s2 += __shfl_down_sync(0xffffffffu, s2, o);
        s3 += __shfl_down_sync(0xffffffffu, s3, o);
    }
    if (lane == 0) {
        if (tbl == 0) { g_er[w] = s0; g_er[NN+w] = s1; g_el[2*NN+w] = s2; g_el[3*NN+w] = s3; }
        else          { g_el[w] = s0; g_el[NN+w] = s1; g_er[2*NN+w] = s2; g_er[3*NN+w] = s3; }
    }
}

// ------------- unified scatter: y in 0..3; GAT or GC per-y (one feature table)
__global__ void __launch_bounds__(256, 6) scatter_k(ScatP P, const float* __restrict__ fsrc) {
    int g = blockIdx.y;
    const int* src = P.src[g];
    const int* dst = P.dst[g];
    float* z = P.z[g];
    __shared__ int   s_si[EB];
    __shared__ int   s_di[EB];
    __shared__ float s_wx[EB];
    int tid = threadIdx.x;
    int ebase = blockIdx.x * EB;
    int nval = EE - ebase; if (nval > EB) nval = EB;
    if (tid < nval) {
        int e = ebase + tid;
        int si = __ldg(src + e), di = __ldg(dst + e);
        float w;
        if (P.gat[g]) {
            float ee = __ldg(P.el[g] + si) + __ldg(P.er[g] + di);
            ee = ee > 0.f ? ee : 0.01f * ee;
            w = __expf(ee);
            atomicAdd(P.s[g] + di, w);
        } else {
            w = rsqrtf(fmaxf(__ldg(P.no[g] + si), 1.f));
        }
        s_si[tid] = si; s_di[tid] = di; s_wx[tid] = w;
    }
    __syncthreads();
    int sub  = tid & 15;
    int half = tid >> 4;
    #pragma unroll
    for (int b = 0; b < 4; b++) {
        float4 fv[4];
        #pragma unroll
        for (int i = 0; i < 4; i++) {
            int le = (b*4 + i)*16 + half;
            if (le < nval)
                fv[i] = __ldg((const float4*)fsrc + (size_t)s_si[le]*16 + sub);
        }
        #pragma unroll
        for (int i = 0; i < 4; i++) {
            int le = (b*4 + i)*16 + half;
            if (le < nval) {
                float x = s_wx[le]; int d = s_di[le]; float4 f = fv[i];
                red4(z + (size_t)d*DD + sub*4, x*f.x, x*f.y, x*f.z, x*f.w);
            }
        }
    }
}

// ------------- unified post: per-y GAT final (div+elu) or GC gemm; + zero next
// grid.x = 3125. GEMM: 16 nodes/block, 2 nodes/warp (halved Wsh LDS wavefronts).
__global__ void __launch_bounds__(256) post_k(PostP P) {
    __shared__ float Wsh[DD*DD];
    int y = blockIdx.y, t = threadIdx.x;
    int idx = blockIdx.x * 256 + t;                       // 3125*256 = 800000 = ZSZ/4
    if (P.mode[y] == 0) {
        float sv = P.s[y][idx >> 4];
        float inv = sv > 0.f ? __frcp_rn(sv) : 0.f;
        float4 v = ((float4*)P.z[y])[idx];
        v.x = elu(v.x * inv); v.y = elu(v.y * inv);
        v.z = elu(v.z * inv); v.w = elu(v.w * inv);
        ((float4*)P.z[y])[idx] = v;
        if (P.zn[y])
            ((float4*)P.zn[y])[idx] = make_float4(0.f,0.f,0.f,0.f);
        return;
    }
    const float* W = P.W[y];
    #pragma unroll
    for (int i = t; i < DD*DD; i += 256) Wsh[i] = W[i];
    __syncthreads();
    int node0 = blockIdx.x * 16 + (t >> 5) * 2;
    int lane = t & 31;
    float* zp0 = P.z[y] + (size_t)node0*DD;
    float* zp1 = zp0 + DD;
    float c0 = rsqrtf(fmaxf(P.ni[y][node0],     1.f));
    float c1 = rsqrtf(fmaxf(P.ni[y][node0 + 1], 1.f));
    float r0 = zp0[lane]*c0, r1 = zp0[lane+32]*c0;
    float r2 = zp1[lane]*c1, r3 = zp1[lane+32]*c1;
    const float* b = P.b[y];
    float bl = b[lane], bh = b[lane+32];
    float a0 = bl, a1 = bh;
    float a2 = bl, a3 = bh;
    #pragma unroll
    for (int d = 0; d < 32; d++) {
        float v0 = __shfl_sync(0xffffffffu, r0, d);
        float v2 = __shfl_sync(0xffffffffu, r2, d);
        float wl = Wsh[d*DD + lane], wh = Wsh[d*DD + lane + 32];
        a0 += v0*wl; a1 += v0*wh;
        a2 += v2*wl; a3 += v2*wh;
    }
    #pragma unroll
    for (int d = 0; d < 32; d++) {
        float v1 = __shfl_sync(0xffffffffu, r1, d);
        float v3 = __shfl_sync(0xffffffffu, r3, d);
        float wl = Wsh[(d+32)*DD + lane], wh = Wsh[(d+32)*DD + lane + 32];
        a0 += v1*wl; a1 += v1*wh;
        a2 += v3*wl; a3 += v3*wh;
    }
    zp0[lane]      = a0 > 0.f ? a0 : expm1f(a0);
    zp0[lane + 32] = a1 > 0.f ? a1 : expm1f(a1);
    zp1[lane]      = a2 > 0.f ? a2 : expm1f(a2);
    zp1[lane + 32] = a3 > 0.f ? a3 : expm1f(a3);
    if (P.zn[y])
        ((float4*)P.zn[y])[idx] = make_float4(0.f,0.f,0.f,0.f);
}

// ---------------------------------------------------- semantic attention score
// 16 node-groups (4 nodes) x 16 h-threads. Each thread: 8 rows (4 nodes x 2
// planes) x 8 h (pairs {2hq+32j}, 8B stride across hq = conflict-free).
// Each W LDS.64 feeds 8 FFMA2; z loaded as float2 (2 d per load).
#define NPB 64
#define ZST 68
__global__ void __launch_bounds__(256) sa_score_k(SaP S) {
    extern __shared__ float sm[];
    float* W1sh = sm;                  // 8192
    float* zsh  = sm + DD*HH;          // 2*64*68
    float* b1sh = zsh + 2*NPB*ZST;     // 128
    float* w2sh = b1sh + HH;           // 128
    float* red  = w2sh + HH;           // 2

    int g = blockIdx.y, t = threadIdx.x;
    for (int i = t; i < DD*HH; i += 256) W1sh[i] = S.W1[g][i];
    if (t < HH) { b1sh[t] = S.b1[g][t]; w2sh[t] = S.w2[g][t]; }
    if (t < 2) red[t] = 0.f;

    int nb = blockIdx.x * NPB;
    const float4* base = (const float4*)(g_z + (size_t)(2*g)*ZSZ);
    for (int idx = t; idx < 2*NPB*16; idx += 256) {
        int p = idx >> 10;
        int n = (idx >> 4) & (NPB-1);
        int v = idx & 15;
        float4 val = make_float4(0.f,0.f,0.f,0.f);
        int gn = nb + n;
        if (gn < NN) val = __ldg(base + (size_t)p*(ZSZ/4) + (size_t)gn*16 + v);
        ((float4*)(zsh + (p*NPB + n)*ZST))[v] = val;
    }
    __syncthreads();

    int ng = t >> 4;        // 0..15 node-group (4 nodes)
    int hq = t & 15;        // 0..15 h-thread; h pairs at 2hq+32j
    ull acc[8][4];
    #pragma unroll
    for (int j = 0; j < 4; j++) {
        ull b = *(const ull*)(b1sh + 2*hq + 32*j);
        #pragma unroll
        for (int r = 0; r < 8; r++) acc[r][j] = b;
    }

    const float* z0 = zsh + (ng*4)*ZST;            // plane0 rows
    const float* z1 = zsh + (NPB + ng*4)*ZST;      // plane1 rows
    for (int dd = 0; dd < DD/2; dd++) {
        ull pe[8], po[8];
        #pragma unroll
        for (int i = 0; i < 4; i++) {
            float2 f0 = *(const float2*)(z0 + i*ZST + 2*dd);
            float2 f1 = *(const float2*)(z1 + i*ZST + 2*dd);
            pe[i]   = pack2(f0.x, f0.x);  po[i]   = pack2(f0.y, f0.y);
            pe[4+i] = pack2(f1.x, f1.x);  po[4+i] = pack2(f1.y, f1.y);
        }
        const float* we_row = W1sh + (2*dd)*HH;
        const float* wo_row = W1sh + (2*dd+1)*HH;
        #pragma unroll
        for (int j = 0; j < 4; j++) {
            ull we = *(const ull*)(we_row + 2*hq + 32*j);
            ull wo = *(const ull*)(wo_row + 2*hq + 32*j);
            #pragma unroll
            for (int r = 0; r < 8; r++) {
                acc[r][j] = ffma2(pe[r], we, acc[r][j]);
                acc[r][j] = ffma2(po[r], wo, acc[r][j]);
            }
        }
    }

    float part0 = 0.f, part1 = 0.f;
    #pragma unroll
    for (int r = 0; r < 8; r++) {
        int node = nb + ng*4 + (r & 3);
        if (node >= NN) continue;
        float sv = 0.f;
        #pragma unroll
        for (int j = 0; j < 4; j++) {
            float wa = w2sh[2*hq + 32*j], wb = w2sh[2*hq + 32*j + 1];
            float lo, hi; unpack2(acc[r][j], lo, hi);
            sv += tanha(lo)*wa + tanha(hi)*wb;
        }
        if (r < 4) part0 += sv; else part1 += sv;
    }
    #pragma unroll
    for (int o = 16; o; o >>= 1) {
        part0 += __shfl_down_sync(0xffffffffu, part0, o);
        part1 += __shfl_down_sync(0xffffffffu, part1, o);
    }
    if ((t & 31) == 0) { atomicAdd(&red[0], part0); atomicAdd(&red[1], part1); }
    __syncthreads();
    if (t == 0) {
        atomicAdd(g_wsum + 2*g,     red[0]);
        atomicAdd(g_wsum + 2*g + 1, red[1]);
    }
}

// ---------------------------------------------- combine (beta computed inline)
__global__ void combine_k(float* __restrict__ out) {
    __shared__ float bsh[8];
    int tt = threadIdx.x;
    if (tt == 0) {
        #pragma unroll
        for (int g = 0; g < 4; g++) {
            float w0 = g_wsum[2*g]   * (1.0f/NN);
            float w1 = g_wsum[2*g+1] * (1.0f/NN);
            float m = fmaxf(w0, w1);
            float e0 = __expf(w0-m), e1 = __expf(w1-m);
            float inv = 1.f/(e0+e1);
            bsh[2*g] = e0*inv; bsh[2*g+1] = e1*inv;
        }
    }
    __syncthreads();
    int t = blockIdx.x * blockDim.x + tt;
    const float4* Z = (const float4*)g_z;
    const size_t Pp = ZSZ/4;
    float4 r;
    if (t < NN*16) {
        float b0=bsh[0], b1=bsh[1], b4=bsh[4], b5=bsh[5];
        float4 x0=Z[t], x1=Z[Pp+t], x4=Z[4*Pp+t], x5=Z[5*Pp+t];
        r.x = b0*x0.x+b1*x1.x+b4*x4.x+b5*x5.x;
        r.y = b0*x0.y+b1*x1.y+b4*x4.y+b5*x5.y;
        r.z = b0*x0.z+b1*x1.z+b4*x4.z+b5*x5.z;
        r.w = b0*x0.w+b1*x1.w+b4*x4.w+b5*x5.w;
    } else {
        size_t u = t - NN*16;
        float b2=bsh[2], b3=bsh[3], b6=bsh[6], b7=bsh[7];
        float4 x2=Z[2*Pp+u], x3=Z[3*Pp+u], x6=Z[6*Pp+u], x7=Z[7*Pp+u];
        r.x = b2*x2.x+b3*x3.x+b6*x6.x+b7*x7.x;
        r.y = b2*x2.y+b3*x3.y+b6*x6.y+b7*x7.y;
        r.z = b2*x2.z+b3*x3.z+b6*x6.z+b7*x7.z;
        r.w = b2*x2.w+b3*x3.w+b6*x6.w+b7*x7.w;
    }
    ((float4*)out)[t] = r;
}

// ============================================================== host launcher
extern "C" void kernel_launch(void* const* d_in, const int* in_sizes, int n_in,
                              void* d_out, int out_size) {
    const float* feat_user = (const float*)d_in[0];
    const float* feat_item = (const float*)d_in[1];
    const float* attn_l    = (const float*)d_in[2];
    const float* attn_r    = (const float*)d_in[3];
    const float* W_gc      = (const float*)d_in[4];
    const float* b_gc      = (const float*)d_in[5];
    const float* sa_rel_W1 = (const float*)d_in[6];
    const float* sa_rel_b1 = (const float*)d_in[7];
    const float* sa_rel_w2 = (const float*)d_in[8];
    const float* sa_u_W1   = (const float*)d_in[9];
    const float* sa_u_b1   = (const float*)d_in[10];
    const float* sa_u_w2   = (const float*)d_in[11];
    const float* sa_i_W1   = (const float*)d_in[12];
    const float* sa_i_b1   = (const float*)d_in[13];
    const float* sa_i_w2   = (const float*)d_in[14];
    const int* rel_u_src   = (const int*)d_in[15];
    const int* rel_u_dst   = (const int*)d_in[16];
    const int* rel_i_src   = (const int*)d_in[17];
    const int* rel_i_dst   = (const int*)d_in[18];
    const int* mp_u_src    = (const int*)d_in[19];
    const int* mp_u_dst    = (const int*)d_in[20];
    const int* mp_i_src    = (const int*)d_in[21];
    const int* mp_i_dst    = (const int*)d_in[22];
    float* out = (float*)d_out;

    G4 C;
    C.s[0]=mp_u_src;    C.d[0]=mp_u_dst;
    C.s[1]=mp_u_src+EE; C.d[1]=mp_u_dst+EE;
    C.s[2]=mp_i_src;    C.d[2]=mp_i_dst;
    C.s[3]=mp_i_src+EE; C.d[3]=mp_i_dst+EE;
    SaP S;
    S.W1[0]=sa_rel_W1; S.b1[0]=sa_rel_b1; S.w2[0]=sa_rel_w2;
    S.W1[1]=sa_rel_W1; S.b1[1]=sa_rel_b1; S.w2[1]=sa_rel_w2;
    S.W1[2]=sa_u_W1;   S.b1[2]=sa_u_b1;   S.w2[2]=sa_u_w2;
    S.W1[3]=sa_i_W1;   S.b1[3]=sa_i_b1;   S.w2[3]=sa_i_w2;

    float* zb;  float* sb;  float* elb; float* erb; float* nob; float* nib;
    cudaGetSymbolAddress((void**)&zb,  g_z);
    cudaGetSymbolAddress((void**)&sb,  g_s);
    cudaGetSymbolAddress((void**)&elb, g_el);
    cudaGetSymbolAddress((void**)&erb, g_er);
    cudaGetSymbolAddress((void**)&nob, g_no);
    cudaGetSymbolAddress((void**)&nib, g_ni);

    const int TB = 256;
    const int SCAT_BLKS = (EE + EB - 1) / EB;   // 1954
    const int POST_BLKS = ZSZ / 4 / TB;         // 3125

    // 1) prologue
    pre_k<<<dim3(6250, 5), TB>>>(zb, feat_user, feat_item, attn_l, attn_r, C);

    // 2) phase A scatter (feat_item)
    ScatP A;
    for (int y = 0; y < 2; y++) {
        A.src[y]=rel_u_src+(size_t)y*EE; A.dst[y]=rel_u_dst+(size_t)y*EE;
        A.el[y]=elb+y*NN; A.er[y]=erb+y*NN; A.s[y]=sb+y*NN; A.no[y]=nullptr;
        A.z[y]=zb+(size_t)y*ZSZ; A.gat[y]=1;
    }
    for (int y = 2; y < 4; y++) {
        int g = y;
        A.src[y]=mp_i_src+(size_t)(y-2)*EE; A.dst[y]=mp_i_dst+(size_t)(y-2)*EE;
        A.el[y]=nullptr; A.er[y]=nullptr; A.s[y]=nullptr; A.no[y]=nob+g*NN;
        A.z[y]=zb+(size_t)(4+g)*ZSZ; A.gat[y]=0;
    }
    scatter_k<<<dim3(SCAT_BLKS, 4), TB>>>(A, feat_item);

    // 3) phase A post
    PostP PA;
    for (int y = 0; y < 2; y++) {
        PA.mode[y]=0; PA.s[y]=sb+y*NN; PA.z[y]=zb+(size_t)y*ZSZ;
        PA.zn[y]=zb+(size_t)(2+y)*ZSZ;
        PA.W[y]=nullptr; PA.b[y]=nullptr; PA.ni[y]=nullptr;
    }
    for (int y = 2; y < 4; y++) {
        int g = y;
        PA.mode[y]=1; PA.s[y]=nullptr; PA.z[y]=zb+(size_t)(4+g)*ZSZ;
        PA.zn[y]=zb+(size_t)(4+(y-2))*ZSZ;
        PA.W[y]=W_gc+g*DD*DD; PA.b[y]=b_gc+g*DD; PA.ni[y]=nib+g*NN;
    }
    post_k<<<dim3(POST_BLKS, 4), TB>>>(PA);

    // 4) phase B scatter (feat_user)
    ScatP B;
    for (int y = 0; y < 2; y++) {
        int g = 2 + y;
        B.src[y]=rel_i_src+(size_t)y*EE; B.dst[y]=rel_i_dst+(size_t)y*EE;
        B.el[y]=elb+g*NN; B.er[y]=erb+g*NN; B.s[y]=sb+g*NN; B.no[y]=nullptr;
        B.z[y]=zb+(size_t)g*ZSZ; B.gat[y]=1;
    }
    for (int y = 2; y < 4; y++) {
        int g = y - 2;
        B.src[y]=mp_u_src+(size_t)g*EE; B.dst[y]=mp_u_dst+(size_t)g*EE;
        B.el[y]=nullptr; B.er[y]=nullptr; B.s[y]=nullptr; B.no[y]=nob+g*NN;
        B.z[y]=zb+(size_t)(4+g)*ZSZ; B.gat[y]=0;
    }
    scatter_k<<<dim3(SCAT_BLKS, 4), TB>>>(B, feat_user);

    // 5) phase B post
    PostP PB;
    for (int y = 0; y < 2; y++) {
        int g = 2 + y;
        PB.mode[y]=0; PB.s[y]=sb+g*NN; PB.z[y]=zb+(size_t)g*ZSZ; PB.zn[y]=nullptr;
        PB.W[y]=nullptr; PB.b[y]=nullptr; PB.ni[y]=nullptr;
    }
    for (int y = 2; y < 4; y++) {
        int g = y - 2;
        PB.mode[y]=1; PB.s[y]=nullptr; PB.z[y]=zb+(size_t)(4+g)*ZSZ; PB.zn[y]=nullptr;
        PB.W[y]=W_gc+g*DD*DD; PB.b[y]=b_gc+g*DD; PB.ni[y]=nib+g*NN;
    }
    post_k<<<dim3(POST_BLKS, 4), TB>>>(PB);

    // 6) semantic attention + combine
    int sa_smem = (DD*HH + 2*NPB*ZST + HH + HH + 2) * sizeof(float);
    cudaFuncSetAttribute(sa_score_k, cudaFuncAttributeMaxDynamicSharedMemorySize, sa_smem);
    sa_score_k<<<dim3((NN + NPB - 1)/NPB, 4), TB, sa_smem>>>(S);

    combine_k<<<2*NN*16/TB, TB>>>(out);
}

// round 15
// speedup vs baseline: 1.0088x; 1.0088x over previous
#include <cuda_runtime.h>

#define NN 50000
#define DD 64
#define HH 128
#define EE 500000
#define ZSZ (NN*DD)
#define EB 256          // edges per scatter block (= blockDim)

typedef unsigned long long ull;

// ---------------------------------------------------------------- scratch
__device__ float g_z[(size_t)8*ZSZ];   // 0-3 GAT planes, 4-7 GC planes
__device__ float g_s[4*NN];
__device__ float g_el[4*NN];
__device__ float g_er[4*NN];
__device__ float g_no[4*NN];
__device__ float g_ni[4*NN];
__device__ float g_wsum[8];

struct G4   { const int* s[4]; const int* d[4]; };
struct SaP  { const float* W1[4]; const float* b1[4]; const float* w2[4]; };
struct ScatP {
    const int* src[4]; const int* dst[4];
    const float* el[4]; const float* er[4];
    float* s[4]; const float* no[4];
    float* z[4];
    int gat[4];
};
struct PostP {
    int mode[4];            // 0 = GAT final, 1 = GC gemm
    const float* s[4];
    float* z[4];
    float* zn[4];           // plane to zero (or null)
    const float* W[4]; const float* b[4]; const float* ni[4];
};

// ---------------------------------------------------------------- utils
__device__ __forceinline__ ull pack2(float a, float b) {
    ull r; asm("mov.b64 %0, {%1,%2};" : "=l"(r) : "f"(a), "f"(b)); return r;
}
__device__ __forceinline__ void unpack2(ull v, float& a, float& b) {
    asm("mov.b64 {%0,%1}, %2;" : "=f"(a), "=f"(b) : "l"(v));
}
__device__ __forceinline__ ull ffma2(ull a, ull b, ull c) {
    ull d; asm("fma.rn.f32x2 %0, %1, %2, %3;" : "=l"(d) : "l"(a), "l"(b), "l"(c));
    return d;
}
__device__ __forceinline__ float tanha(float x) {
    float r; asm("tanh.approx.f32 %0, %1;" : "=f"(r) : "f"(x)); return r;
}
__device__ __forceinline__ float elu(float x) { return x > 0.f ? x : expm1f(x); }
__device__ __forceinline__ void red4(float* p, float a, float b, float c, float d) {
    asm volatile("red.global.add.v4.f32 [%0], {%1, %2, %3, %4};"
                 :: "l"(p), "f"(a), "f"(b), "f"(c), "f"(d));   // no mem clobber: keep MLP
}

// -------- fused prologue: y0 zero planes0/1+nodes; y1/y2 ler; y3 deg; y4 zero 6/7
__global__ void pre_k(float* __restrict__ zb,
                      const float* __restrict__ feat_user,
                      const float* __restrict__ feat_item,
                      const float* __restrict__ attn_l,
                      const float* __restrict__ attn_r,
                      G4 C) {
    int y = blockIdx.y;
    int gid = blockIdx.x * blockDim.x + threadIdx.x;      // up to 1.6M
    if (y == 0) {
        ((float4*)zb)[gid] = make_float4(0.f,0.f,0.f,0.f);   // planes 0,1
        if (gid < 4*NN) { g_s[gid] = 0.f; g_no[gid] = 0.f; g_ni[gid] = 0.f; }
        if (gid < 8) g_wsum[gid] = 0.f;
        return;
    }
    if (y == 4) {
        ((float4*)(zb + (size_t)6*ZSZ))[gid] = make_float4(0.f,0.f,0.f,0.f); // planes 6,7
        return;
    }
    if (y == 3) {
        #pragma unroll
        for (int k = 0; k < 2; k++) {
            int i = gid + k * 1600000;
            if (i < 4*EE) {
                int g = i / EE, e = i - g*EE;
                atomicAdd(g_no + g*NN + __ldg(C.s[g] + e), 1.f);
                atomicAdd(g_ni + g*NN + __ldg(C.d[g] + e), 1.f);
            }
        }
        return;
    }
    int tbl = y - 1;
    int w = gid >> 5;
    int lane = threadIdx.x & 31;
    const float* f = (tbl == 0 ? feat_user : feat_item) + (size_t)w * DD;
    float f0 = f[lane], f1 = f[lane + 32];
    const float* v0; const float* v1; const float* v2; const float* v3;
    if (tbl == 0) { v0 = attn_r; v1 = attn_r + DD; v2 = attn_l + 2*DD; v3 = attn_l + 3*DD; }
    else          { v0 = attn_l; v1 = attn_l + DD; v2 = attn_r + 2*DD; v3 = attn_r + 3*DD; }
    float s0 = f0*__ldg(v0+lane) + f1*__ldg(v0+lane+32);
    float s1 = f0*__ldg(v1+lane) + f1*__ldg(v1+lane+32);
    float s2 = f0*__ldg(v2+lane) + f1*__ldg(v2+lane+32);
    float s3 = f0*__ldg(v3+lane) + f1*__ldg(v3+lane+32);
    #pragma unroll
    for (int o = 16; o; o >>= 1) {
        s0 += __shfl_down_sync(0xffffffffu, s0, o);
        s1 += __shfl_down_sync(0xffffffffu, s1, o);
        s2 += __shfl_down_sync(0xffffffffu, s2, o);
        s3 += __shfl_down_sync(0xffffffffu, s3, o);
    }
    if (lane == 0) {
        if (tbl == 0) { g_er[w] = s0; g_er[NN+w] = s1; g_el[2*NN+w] = s2; g_el[3*NN+w] = s3; }
        else          { g_el[w] = s0; g_el[NN+w] = s1; g_er[2*NN+w] = s2; g_er[3*NN+w] = s3; }
    }
}

// ------------- unified scatter: y in 0..3; GAT or GC per-y (one feature table)
__global__ void __launch_bounds__(256, 6) scatter_k(ScatP P, const float* __restrict__ fsrc) {
    int g = blockIdx.y;
    const int* src = P.src[g];
    const int* dst = P.dst[g];
    float* z = P.z[g];
    __shared__ int   s_si[EB];
    __shared__ int   s_di[EB];
    __shared__ float s_wx[EB];
    int tid = threadIdx.x;
    int ebase = blockIdx.x * EB;
    int nval = EE - ebase; if (nval > EB) nval = EB;
    if (tid < nval) {
        int e = ebase + tid;
        int si = __ldg(src + e), di = __ldg(dst + e);
        float w;
        if (P.gat[g]) {
            float ee = __ldg(P.el[g] + si) + __ldg(P.er[g] + di);
            ee = ee > 0.f ? ee : 0.01f * ee;
            w = __expf(ee);
            atomicAdd(P.s[g] + di, w);
        } else {
            w = rsqrtf(fmaxf(__ldg(P.no[g] + si), 1.f));
        }
        s_si[tid] = si; s_di[tid] = di; s_wx[tid] = w;
    }
    __syncthreads();
    int sub  = tid & 15;
    int half = tid >> 4;
    #pragma unroll
    for (int b = 0; b < 4; b++) {
        float4 fv[4];
        #pragma unroll
        for (int i = 0; i < 4; i++) {
            int le = (b*4 + i)*16 + half;
            if (le < nval)
                fv[i] = __ldg((const float4*)fsrc + (size_t)s_si[le]*16 + sub);
        }
        #pragma unroll
        for (int i = 0; i < 4; i++) {
            int le = (b*4 + i)*16 + half;
            if (le < nval) {
                float x = s_wx[le]; int d = s_di[le]; float4 f = fv[i];
                red4(z + (size_t)d*DD + sub*4, x*f.x, x*f.y, x*f.z, x*f.w);
            }
        }
    }
}

// ------------- unified post: per-y GAT final (div+elu) or GC gemm; + zero next
// grid.x = 3125. GEMM: 16 nodes/block, 2 nodes/warp (halved Wsh LDS wavefronts).
__global__ void __launch_bounds__(256) post_k(PostP P) {
    __shared__ float Wsh[DD*DD];
    int y = blockIdx.y, t = threadIdx.x;
    int idx = blockIdx.x * 256 + t;                       // 3125*256 = 800000 = ZSZ/4
    if (P.mode[y] == 0) {
        float sv = P.s[y][idx >> 4];
        float inv = sv > 0.f ? __frcp_rn(sv) : 0.f;
        float4 v = ((float4*)P.z[y])[idx];
        v.x = elu(v.x * inv); v.y = elu(v.y * inv);
        v.z = elu(v.z * inv); v.w = elu(v.w * inv);
        ((float4*)P.z[y])[idx] = v;
        if (P.zn[y])
            ((float4*)P.zn[y])[idx] = make_float4(0.f,0.f,0.f,0.f);
        return;
    }
    const float* W = P.W[y];
    #pragma unroll
    for (int i = t; i < DD*DD; i += 256) Wsh[i] = W[i];
    __syncthreads();
    int node0 = blockIdx.x * 16 + (t >> 5) * 2;
    int lane = t & 31;
    float* zp0 = P.z[y] + (size_t)node0*DD;
    float* zp1 = zp0 + DD;
    float c0 = rsqrtf(fmaxf(P.ni[y][node0],     1.f));
    float c1 = rsqrtf(fmaxf(P.ni[y][node0 + 1], 1.f));
    float r0 = zp0[lane]*c0, r1 = zp0[lane+32]*c0;
    float r2 = zp1[lane]*c1, r3 = zp1[lane+32]*c1;
    const float* b = P.b[y];
    float bl = b[lane], bh = b[lane+32];
    float a0 = bl, a1 = bh;
    float a2 = bl, a3 = bh;
    #pragma unroll
    for (int d = 0; d < 32; d++) {
        float v0 = __shfl_sync(0xffffffffu, r0, d);
        float v2 = __shfl_sync(0xffffffffu, r2, d);
        float wl = Wsh[d*DD + lane], wh = Wsh[d*DD + lane + 32];
        a0 += v0*wl; a1 += v0*wh;
        a2 += v2*wl; a3 += v2*wh;
    }
    #pragma unroll
    for (int d = 0; d < 32; d++) {
        float v1 = __shfl_sync(0xffffffffu, r1, d);
        float v3 = __shfl_sync(0xffffffffu, r3, d);
        float wl = Wsh[(d+32)*DD + lane], wh = Wsh[(d+32)*DD + lane + 32];
        a0 += v1*wl; a1 += v1*wh;
        a2 += v3*wl; a3 += v3*wh;
    }
    zp0[lane]      = a0 > 0.f ? a0 : expm1f(a0);
    zp0[lane + 32] = a1 > 0.f ? a1 : expm1f(a1);
    zp1[lane]      = a2 > 0.f ? a2 : expm1f(a2);
    zp1[lane + 32] = a3 > 0.f ? a3 : expm1f(a3);
    if (P.zn[y])
        ((float4*)P.zn[y])[idx] = make_float4(0.f,0.f,0.f,0.f);
}

// ---------------------------------------------------- semantic attention score
// R13-proven layout: 32 node-pairs x 8 h-threads; thread owns h pairs {2hq+16j}
// -> conflict-free LDS.64. Two attention groups per launch via blockIdx.y.
#define NPB 64
#define ZST 68
__global__ void __launch_bounds__(256) sa_pair_k(SaP S, int ga, int gb) {
    extern __shared__ float sm[];
    float* W1sh = sm;                  // 8192
    float* zsh  = sm + DD*HH;          // 2*64*68
    float* b1sh = zsh + 2*NPB*ZST;     // 128
    float* w2sh = b1sh + HH;           // 128
    float* red  = w2sh + HH;           // 2

    int g = blockIdx.y == 0 ? ga : gb;
    int t = threadIdx.x;
    for (int i = t; i < DD*HH; i += 256) W1sh[i] = S.W1[g][i];
    if (t < HH) { b1sh[t] = S.b1[g][t]; w2sh[t] = S.w2[g][t]; }
    if (t < 2) red[t] = 0.f;

    int nb = blockIdx.x * NPB;
    const float4* base = (const float4*)(g_z + (size_t)(2*g)*ZSZ);
    for (int idx = t; idx < 2*NPB*16; idx += 256) {
        int p = idx >> 10;
        int n = (idx >> 4) & (NPB-1);
        int v = idx & 15;
        float4 val = make_float4(0.f,0.f,0.f,0.f);
        int gn = nb + n;
        if (gn < NN) val = __ldg(base + (size_t)p*(ZSZ/4) + (size_t)gn*16 + v);
        ((float4*)(zsh + (p*NPB + n)*ZST))[v] = val;
    }
    __syncthreads();

    int pair = t >> 3;
    int hq   = t & 7;
    ull acc[4][8];
    #pragma unroll
    for (int j = 0; j < 8; j++) {
        ull b = *(const ull*)(b1sh + 2*hq + 16*j);
        acc[0][j] = b; acc[1][j] = b; acc[2][j] = b; acc[3][j] = b;
    }

    const float* z0 = zsh + (pair*2)*ZST;
    const float* z1 = zsh + (NPB + pair*2)*ZST;
    for (int d = 0; d < DD; d++) {
        float a0 = z0[d], a1 = z0[ZST + d];
        float c0 = z1[d], c1 = z1[ZST + d];
        ull p0 = pack2(a0, a0), p1 = pack2(a1, a1);
        ull p2 = pack2(c0, c0), p3 = pack2(c1, c1);
        const float* wrow = W1sh + d*HH;
        #pragma unroll
        for (int j = 0; j < 8; j++) {
            ull w = *(const ull*)(wrow + 2*hq + 16*j);
            acc[0][j] = ffma2(p0, w, acc[0][j]);
            acc[1][j] = ffma2(p1, w, acc[1][j]);
            acc[2][j] = ffma2(p2, w, acc[2][j]);
            acc[3][j] = ffma2(p3, w, acc[3][j]);
        }
    }

    float part0 = 0.f, part1 = 0.f;
    #pragma unroll
    for (int r = 0; r < 4; r++) {
        int node = nb + pair*2 + (r & 1);
        if (node >= NN) continue;
        float sv = 0.f;
        #pragma unroll
        for (int j = 0; j < 8; j++) {
            float wa = w2sh[2*hq + 16*j], wb = w2sh[2*hq + 16*j + 1];
            float lo, hi; unpack2(acc[r][j], lo, hi);
            sv += tanha(lo)*wa + tanha(hi)*wb;
        }
        if (r < 2) part0 += sv; else part1 += sv;
    }
    #pragma unroll
    for (int o = 16; o; o >>= 1) {
        part0 += __shfl_down_sync(0xffffffffu, part0, o);
        part1 += __shfl_down_sync(0xffffffffu, part1, o);
    }
    if ((t & 31) == 0) { atomicAdd(&red[0], part0); atomicAdd(&red[1], part1); }
    __syncthreads();
    if (t == 0) {
        atomicAdd(g_wsum + 2*g,     red[0]);
        atomicAdd(g_wsum + 2*g + 1, red[1]);
    }
}

// ---------------------------------------------- combine (beta computed inline)
__global__ void combine_k(float* __restrict__ out) {
    __shared__ float bsh[8];
    int tt = threadIdx.x;
    if (tt == 0) {
        #pragma unroll
        for (int g = 0; g < 4; g++) {
            float w0 = g_wsum[2*g]   * (1.0f/NN);
            float w1 = g_wsum[2*g+1] * (1.0f/NN);
            float m = fmaxf(w0, w1);
            float e0 = __expf(w0-m), e1 = __expf(w1-m);
            float inv = 1.f/(e0+e1);
            bsh[2*g] = e0*inv; bsh[2*g+1] = e1*inv;
        }
    }
    __syncthreads();
    int t = blockIdx.x * blockDim.x + tt;
    const float4* Z = (const float4*)g_z;
    const size_t Pp = ZSZ/4;
    float4 r;
    if (t < NN*16) {
        float b0=bsh[0], b1=bsh[1], b4=bsh[4], b5=bsh[5];
        float4 x0=Z[t], x1=Z[Pp+t], x4=Z[4*Pp+t], x5=Z[5*Pp+t];
        r.x = b0*x0.x+b1*x1.x+b4*x4.x+b5*x5.x;
        r.y = b0*x0.y+b1*x1.y+b4*x4.y+b5*x5.y;
        r.z = b0*x0.z+b1*x1.z+b4*x4.z+b5*x5.z;
        r.w = b0*x0.w+b1*x1.w+b4*x4.w+b5*x5.w;
    } else {
        size_t u = t - NN*16;
        float b2=bsh[2], b3=bsh[3], b6=bsh[6], b7=bsh[7];
        float4 x2=Z[2*Pp+u], x3=Z[3*Pp+u], x6=Z[6*Pp+u], x7=Z[7*Pp+u];
        r.x = b2*x2.x+b3*x3.x+b6*x6.x+b7*x7.x;
        r.y = b2*x2.y+b3*x3.y+b6*x6.y+b7*x7.y;
        r.z = b2*x2.z+b3*x3.z+b6*x6.z+b7*x7.z;
        r.w = b2*x2.w+b3*x3.w+b6*x6.w+b7*x7.w;
    }
    ((float4*)out)[t] = r;
}

// ============================================================== host launcher
extern "C" void kernel_launch(void* const* d_in, const int* in_sizes, int n_in,
                              void* d_out, int out_size) {
    const float* feat_user = (const float*)d_in[0];
    const float* feat_item = (const float*)d_in[1];
    const float* attn_l    = (const float*)d_in[2];
    const float* attn_r    = (const float*)d_in[3];
    const float* W_gc      = (const float*)d_in[4];
    const float* b_gc      = (const float*)d_in[5];
    const float* sa_rel_W1 = (const float*)d_in[6];
    const float* sa_rel_b1 = (const float*)d_in[7];
    const float* sa_rel_w2 = (const float*)d_in[8];
    const float* sa_u_W1   = (const float*)d_in[9];
    const float* sa_u_b1   = (const float*)d_in[10];
    const float* sa_u_w2   = (const float*)d_in[11];
    const float* sa_i_W1   = (const float*)d_in[12];
    const float* sa_i_b1   = (const float*)d_in[13];
    const float* sa_i_w2   = (const float*)d_in[14];
    const int* rel_u_src   = (const int*)d_in[15];
    const int* rel_u_dst   = (const int*)d_in[16];
    const int* rel_i_src   = (const int*)d_in[17];
    const int* rel_i_dst   = (const int*)d_in[18];
    const int* mp_u_src    = (const int*)d_in[19];
    const int* mp_u_dst    = (const int*)d_in[20];
    const int* mp_i_src    = (const int*)d_in[21];
    const int* mp_i_dst    = (const int*)d_in[22];
    float* out = (float*)d_out;

    G4 C;
    C.s[0]=mp_u_src;    C.d[0]=mp_u_dst;
    C.s[1]=mp_u_src+EE; C.d[1]=mp_u_dst+EE;
    C.s[2]=mp_i_src;    C.d[2]=mp_i_dst;
    C.s[3]=mp_i_src+EE; C.d[3]=mp_i_dst+EE;
    SaP S;
    S.W1[0]=sa_rel_W1; S.b1[0]=sa_rel_b1; S.w2[0]=sa_rel_w2;
    S.W1[1]=sa_rel_W1; S.b1[1]=sa_rel_b1; S.w2[1]=sa_rel_w2;
    S.W1[2]=sa_u_W1;   S.b1[2]=sa_u_b1;   S.w2[2]=sa_u_w2;
    S.W1[3]=sa_i_W1;   S.b1[3]=sa_i_b1;   S.w2[3]=sa_i_w2;

    float* zb;  float* sb;  float* elb; float* erb; float* nob; float* nib;
    cudaGetSymbolAddress((void**)&zb,  g_z);
    cudaGetSymbolAddress((void**)&sb,  g_s);
    cudaGetSymbolAddress((void**)&elb, g_el);
    cudaGetSymbolAddress((void**)&erb, g_er);
    cudaGetSymbolAddress((void**)&nob, g_no);
    cudaGetSymbolAddress((void**)&nib, g_ni);

    const int TB = 256;
    const int SCAT_BLKS = (EE + EB - 1) / EB;   // 1954
    const int POST_BLKS = ZSZ / 4 / TB;         // 3125
    const int SAB = (NN + NPB - 1) / NPB;       // 782

    int sa_smem = (DD*HH + 2*NPB*ZST + HH + HH + 2) * sizeof(float);
    cudaFuncSetAttribute(sa_pair_k, cudaFuncAttributeMaxDynamicSharedMemorySize, sa_smem);

    // fork-join stream + events (created per call; kernel_launch runs only twice)
    cudaStream_t s2 = 0;
    cudaEvent_t evA = 0, evS = 0;
    bool fork_ok =
        cudaStreamCreateWithFlags(&s2, cudaStreamNonBlocking) == cudaSuccess &&
        cudaEventCreateWithFlags(&evA, cudaEventDisableTiming) == cudaSuccess &&
        cudaEventCreateWithFlags(&evS, cudaEventDisableTiming) == cudaSuccess;

    // 1) prologue
    pre_k<<<dim3(6250, 5), TB>>>(zb, feat_user, feat_item, attn_l, attn_r, C);

    // 2) phase A scatter (feat_item): GAT g0,g1 -> planes 0,1 ; GC g2,g3 -> planes 6,7
    ScatP A;
    for (int y = 0; y < 2; y++) {
        A.src[y]=rel_u_src+(size_t)y*EE; A.dst[y]=rel_u_dst+(size_t)y*EE;
        A.el[y]=elb+y*NN; A.er[y]=erb+y*NN; A.s[y]=sb+y*NN; A.no[y]=nullptr;
        A.z[y]=zb+(size_t)y*ZSZ; A.gat[y]=1;
    }
    for (int y = 2; y < 4; y++) {
        int g = y;
        A.src[y]=mp_i_src+(size_t)(y-2)*EE; A.dst[y]=mp_i_dst+(size_t)(y-2)*EE;
        A.el[y]=nullptr; A.er[y]=nullptr; A.s[y]=nullptr; A.no[y]=nob+g*NN;
        A.z[y]=zb+(size_t)(4+g)*ZSZ; A.gat[y]=0;
    }
    scatter_k<<<dim3(SCAT_BLKS, 4), TB>>>(A, feat_item);

    // 3) phase A post: finals planes 0,1 (zero 2,3) ; gemms planes 6,7 (zero 4,5)
    PostP PA;
    for (int y = 0; y < 2; y++) {
        PA.mode[y]=0; PA.s[y]=sb+y*NN; PA.z[y]=zb+(size_t)y*ZSZ;
        PA.zn[y]=zb+(size_t)(2+y)*ZSZ;
        PA.W[y]=nullptr; PA.b[y]=nullptr; PA.ni[y]=nullptr;
    }
    for (int y = 2; y < 4; y++) {
        int g = y;
        PA.mode[y]=1; PA.s[y]=nullptr; PA.z[y]=zb+(size_t)(4+g)*ZSZ;
        PA.zn[y]=zb+(size_t)(4+(y-2))*ZSZ;
        PA.W[y]=W_gc+g*DD*DD; PA.b[y]=b_gc+g*DD; PA.ni[y]=nib+g*NN;
    }
    post_k<<<dim3(POST_BLKS, 4), TB>>>(PA);

    // fork: sa for groups 0 (planes 0,1) and 3 (planes 6,7) — ready after postA
    if (fork_ok) {
        cudaEventRecord(evA, 0);
        cudaStreamWaitEvent(s2, evA, 0);
        sa_pair_k<<<dim3(SAB, 2), TB, sa_smem, s2>>>(S, 0, 3);
        cudaEventRecord(evS, s2);
    }

    // 4) phase B scatter (feat_user): GAT g2,g3 -> planes 2,3 ; GC g0,g1 -> planes 4,5
    ScatP B;
    for (int y = 0; y < 2; y++) {
        int g = 2 + y;
        B.src[y]=rel_i_src+(size_t)y*EE; B.dst[y]=rel_i_dst+(size_t)y*EE;
        B.el[y]=elb+g*NN; B.er[y]=erb+g*NN; B.s[y]=sb+g*NN; B.no[y]=nullptr;
        B.z[y]=zb+(size_t)g*ZSZ; B.gat[y]=1;
    }
    for (int y = 2; y < 4; y++) {
        int g = y - 2;
        B.src[y]=mp_u_src+(size_t)g*EE; B.dst[y]=mp_u_dst+(size_t)g*EE;
        B.el[y]=nullptr; B.er[y]=nullptr; B.s[y]=nullptr; B.no[y]=nob+g*NN;
        B.z[y]=zb+(size_t)(4+g)*ZSZ; B.gat[y]=0;
    }
    scatter_k<<<dim3(SCAT_BLKS, 4), TB>>>(B, feat_user);

    // 5) phase B post: finals planes 2,3 ; gemms planes 4,5
    PostP PB;
    for (int y = 0; y < 2; y++) {
        int g = 2 + y;
        PB.mode[y]=0; PB.s[y]=sb+g*NN; PB.z[y]=zb+(size_t)g*ZSZ; PB.zn[y]=nullptr;
        PB.W[y]=nullptr; PB.b[y]=nullptr; PB.ni[y]=nullptr;
    }
    for (int y = 2; y < 4; y++) {
        int g = y - 2;
        PB.mode[y]=1; PB.s[y]=nullptr; PB.z[y]=zb+(size_t)(4+g)*ZSZ; PB.zn[y]=nullptr;
        PB.W[y]=W_gc+g*DD*DD; PB.b[y]=b_gc+g*DD; PB.ni[y]=nib+g*NN;
    }
    post_k<<<dim3(POST_BLKS, 4), TB>>>(PB);

    // join + remaining sa
    if (fork_ok) {
        cudaStreamWaitEvent(0, evS, 0);
        sa_pair_k<<<dim3(SAB, 2), TB, sa_smem>>>(S, 1, 2);
    } else {
        sa_pair_k<<<dim3(SAB, 2), TB, sa_smem>>>(S, 0, 3);
        sa_pair_k<<<dim3(SAB, 2), TB, sa_smem>>>(S, 1, 2);
    }

    // 6) combine
    combine_k<<<2*NN*16/TB, TB>>>(out);
}